// round 3
// baseline (speedup 1.0000x reference)
#include <cuda_runtime.h>
#include <math.h>

// ---------------- Problem constants ----------------
#define BCH   8
#define NS    2097152
#define LBLK  128                 // samples per block
#define KPC   (NS/LBLK)           // 16384 blocks per channel
#define NBLK  (BCH*KPC)           // 131072 blocks total
#define TPB   128                 // threads per CTA (phase kernels)
#define BLKS_PER_CTA (2*TPB)      // 256 blocks per CTA (f32x2 pairing, adjacent)
#define NCTA  (NBLK/BLKS_PER_CTA) // 512 CTAs
#define CHUNK 16                  // samples staged per chunk
#define NCHUNK (LBLK/CHUNK)       // 8 chunks
#define RPAD  258                 // column stride (even for LDS.64, conflict-free)
#define DTR   14                  // warmup depth: 0.397^14 ~ 2.4e-6
#define CHAIN 8                   // blocks propagated serially per scan chain
#define PI_D  3.14159265358979323846
#define SR_D  44100.0

// ---------------- Device scratch ----------------
__device__ float  g_coef[5][5];        // b0, p1, p2, -a1, -a2 per biquad
__device__ float  g_M[100];            // M = A^LBLK (10x10)
__device__ float2 g_fp[5][NBLK];       // zero-state final state per block, per stage (s1,s2)
__device__ float2 g_s0p[5][NBLK];      // reconstructed initial state per block, per stage

typedef unsigned long long ull;

// ---------------- f32x2 packed math (sm_103a) ----------------
__device__ __forceinline__ ull pk2(float lo, float hi) {
    ull r; asm("mov.b64 %0, {%1,%2};" : "=l"(r) : "f"(lo), "f"(hi)); return r;
}
__device__ __forceinline__ void upk2(ull v, float& lo, float& hi) {
    asm("mov.b64 {%0,%1}, %2;" : "=f"(lo), "=f"(hi) : "l"(v));
}
__device__ __forceinline__ ull fma2(ull a, ull b, ull c) {
    ull d; asm("fma.rn.f32x2 %0, %1, %2, %3;" : "=l"(d) : "l"(a), "l"(b), "l"(c)); return d;
}
__device__ __forceinline__ ull mul2(ull a, ull b) {
    ull d; asm("mul.rn.f32x2 %0, %1, %2;" : "=l"(d) : "l"(a), "l"(b)); return d;
}

// ---------------- Setup: coeffs + A + M = A^128 ----------------
__global__ void eq_setup_kernel(const float* __restrict__ eq) {
    __shared__ double sc[5][5];
    __shared__ double Abuf[100], Ma[100], Mb[100];
    int t = threadIdx.x;

    if (t < 5) {
        int i = t;
        double g = (double)eq[i*3+0], fc = (double)eq[i*3+1], q = (double)eq[i*3+2];
        double Av = pow(10.0, g / 40.0);
        double w0 = 2.0 * PI_D * fc / SR_D;
        double al = sin(w0) / (2.0 * q);
        double c  = cos(w0);
        double b0, b1, b2, a0, a1, a2;
        if (i == 0 || i == 4) {
            double sgn = (i == 4) ? 1.0 : -1.0;
            double sA = sqrt(Av);
            b0 = Av * ((Av + 1.0) + sgn * (Av - 1.0) * c + 2.0 * sA * al);
            b1 = -2.0 * sgn * Av * ((Av - 1.0) + sgn * (Av + 1.0) * c);
            b2 = Av * ((Av + 1.0) + sgn * (Av - 1.0) * c - 2.0 * sA * al);
            a0 = (Av + 1.0) - sgn * (Av - 1.0) * c + 2.0 * sA * al;
            a1 = 2.0 * sgn * ((Av - 1.0) - sgn * (Av + 1.0) * c);
            a2 = (Av + 1.0) - sgn * (Av - 1.0) * c - 2.0 * sA * al;
        } else {
            b0 = 1.0 + al * Av; b1 = -2.0 * c; b2 = 1.0 - al * Av;
            a0 = 1.0 + al / Av; a1 = -2.0 * c; a2 = 1.0 - al / Av;
        }
        double b0n = b0/a0, b1n = b1/a0, b2n = b2/a0, a1n = a1/a0, a2n = a2/a0;
        sc[i][0] = b0n; sc[i][1] = b1n; sc[i][2] = b2n; sc[i][3] = a1n; sc[i][4] = a2n;
        g_coef[i][0] = (float)b0n;
        g_coef[i][1] = (float)(b1n - a1n * b0n);   // p1
        g_coef[i][2] = (float)(b2n - a2n * b0n);   // p2
        g_coef[i][3] = (float)(-a1n);
        g_coef[i][4] = (float)(-a2n);
    }
    __syncthreads();

    if (t == 0) {
        // Homogeneous transition A for DF2T cascade state (s1_1,s2_1,...,s1_5,s2_5)
        double U[10]; for (int j = 0; j < 10; j++) U[j] = 0.0;
        for (int j = 0; j < 100; j++) Abuf[j] = 0.0;
        for (int i = 0; i < 5; i++) {
            double b0 = sc[i][0], b1 = sc[i][1], b2 = sc[i][2], a1 = sc[i][3], a2 = sc[i][4];
            double p1 = b1 - a1 * b0, p2 = b2 - a2 * b0;
            for (int j = 0; j < 10; j++) {
                Abuf[(2*i)*10 + j]   += p1 * U[j];
                Abuf[(2*i+1)*10 + j] += p2 * U[j];
            }
            Abuf[(2*i)*10 + 2*i]     += -a1;
            Abuf[(2*i)*10 + 2*i + 1] += 1.0;
            Abuf[(2*i+1)*10 + 2*i]   += -a2;
            for (int j = 0; j < 10; j++) U[j] *= b0;
            U[2*i] += 1.0;
        }
    }
    __syncthreads();

    if (t < 100) Ma[t] = Abuf[t];
    __syncthreads();

    // M = A^128 via 7 squarings (100-thread parallel)
    double* src = Ma; double* dst = Mb;
    for (int s = 0; s < 7; s++) {
        if (t < 100) {
            int r = t / 10, c = t % 10;
            double acc = 0.0;
            for (int k = 0; k < 10; k++) acc += src[r*10 + k] * src[k*10 + c];
            dst[t] = acc;
        }
        __syncthreads();
        double* tmp = src; src = dst; dst = tmp;
    }
    if (t < 100) g_M[t] = (float)src[t];
}

// ---------------- Cascade (state-space form, 4-cycle recurrence chain) ----------------
struct Coefs { ull b0[5], p1[5], p2[5], na1[5], na2[5]; };

__device__ __forceinline__ void load_coefs(Coefs& C) {
#pragma unroll
    for (int i = 0; i < 5; i++) {
        float b0 = g_coef[i][0], p1 = g_coef[i][1], p2 = g_coef[i][2];
        float na1 = g_coef[i][3], na2 = g_coef[i][4];
        C.b0[i] = pk2(b0, b0); C.p1[i] = pk2(p1, p1); C.p2[i] = pk2(p2, p2);
        C.na1[i] = pk2(na1, na1); C.na2[i] = pk2(na2, na2);
    }
}

__device__ __forceinline__ ull cascade_step(const Coefs& C, ull u, ull s1[5], ull s2[5]) {
#pragma unroll
    for (int i = 0; i < 5; i++) {
        ull y   = fma2(C.b0[i], u, s1[i]);          // output (off state chain)
        ull tt  = fma2(C.p1[i], u, s2[i]);          // off-chain
        ull w   = mul2(C.p2[i], u);                 // off-chain
        ull s1n = fma2(C.na1[i], s1[i], tt);        // chain: s1 -> s1' (4 cyc)
        s2[i]   = fma2(C.na2[i], s1[i], w);
        s1[i]   = s1n;
        u = y;
    }
    return u;
}

// ---------------- Phase 1: zero-state recurrence, emit final states ----------------
__global__ void __launch_bounds__(TPB, 4) eq_phase1_kernel(const float* __restrict__ x) {
    extern __shared__ float sx[];                 // [CHUNK][RPAD]
    const int t = threadIdx.x;
    const long base = (long)blockIdx.x * (BLKS_PER_CTA * LBLK);

    Coefs C; load_coefs(C);
    ull s1[5] = {0,0,0,0,0}, s2[5] = {0,0,0,0,0};

    float4 pf[8];
#pragma unroll
    for (int j = 0; j < 8; j++) {
        int idx = j * TPB + t; int br = idx >> 2, cg = idx & 3;
        pf[j] = *(const float4*)(x + base + (long)br * LBLK + cg * 4);
    }

    for (int q = 0; q < NCHUNK; q++) {
#pragma unroll
        for (int j = 0; j < 8; j++) {
            int idx = j * TPB + t; int br = idx >> 2, cg = idx & 3;
            float4 v = pf[j];
            sx[(cg*4+0)*RPAD + br] = v.x;
            sx[(cg*4+1)*RPAD + br] = v.y;
            sx[(cg*4+2)*RPAD + br] = v.z;
            sx[(cg*4+3)*RPAD + br] = v.w;
        }
        __syncthreads();
        if (q + 1 < NCHUNK) {
#pragma unroll
            for (int j = 0; j < 8; j++) {
                int idx = j * TPB + t; int br = idx >> 2, cg = idx & 3;
                pf[j] = *(const float4*)(x + base + (long)br * LBLK + (q+1) * CHUNK + cg * 4);
            }
        }
#pragma unroll
        for (int c = 0; c < CHUNK; c++) {
            ull u = *(const ull*)(sx + c * RPAD + 2 * t);   // LDS.64: both lanes
            (void)cascade_step(C, u, s1, s2);
        }
        __syncthreads();
    }

    const int b0i = blockIdx.x * BLKS_PER_CTA + 2 * t;      // adjacent pair
#pragma unroll
    for (int i = 0; i < 5; i++) {
        float s1lo, s1hi, s2lo, s2hi;
        upk2(s1[i], s1lo, s1hi); upk2(s2[i], s2lo, s2hi);
        float4 v = make_float4(s1lo, s2lo, s1hi, s2hi);
        *(float4*)&g_fp[i][b0i] = v;                         // 16B aligned (b0i even)
    }
}

// ---------------- Phase 2: chained scan ----------------
// Each thread handles 2 chains (lo=2p, hi=2p+1) of CHAIN consecutive blocks.
// Warmup: truncated Horner over DTR prior blocks, then serial s0[k+1]=M*s0[k]+f[k].
__global__ void __launch_bounds__(128) eq_scan_kernel() {
    __shared__ ull sM[100];
    const int t = threadIdx.x;
    if (t < 100) { float m = g_M[t]; sM[t] = pk2(m, m); }
    __syncthreads();

    const int p = blockIdx.x * 128 + t;
    const int j_lo = (2 * p) * CHAIN;          // start block of lo chain
    const int ch0 = j_lo & ~(KPC - 1);         // channel start (chains never straddle)

    ull s[10];
#pragma unroll
    for (int j = 0; j < 10; j++) s[j] = 0;

    // Warmup: k = j_lo-DTR .. j_lo-1 :  s = M*s + f[k]
#pragma unroll 1
    for (int k = j_lo - DTR; k < j_lo; k++) {
        ull f[10];
#pragma unroll
        for (int i = 0; i < 5; i++) {
            float2 flo = (k >= ch0) ? g_fp[i][k] : make_float2(0.f, 0.f);
            float2 fhi = (k + CHAIN >= ch0) ? g_fp[i][k + CHAIN] : make_float2(0.f, 0.f);
            f[2*i]   = pk2(flo.x, fhi.x);
            f[2*i+1] = pk2(flo.y, fhi.y);
        }
        ull ns[10];
#pragma unroll
        for (int r = 0; r < 10; r++) {
            ull acc = f[r];
#pragma unroll
            for (int c = 0; c < 10; c++) acc = fma2(sM[r*10 + c], s[c], acc);
            ns[r] = acc;
        }
#pragma unroll
        for (int j = 0; j < 10; j++) s[j] = ns[j];
    }

    // Emit + propagate through CHAIN blocks
#pragma unroll 1
    for (int i = 0; i < CHAIN; i++) {
        int k = j_lo + i;
#pragma unroll
        for (int st = 0; st < 5; st++) {
            float s1lo, s1hi, s2lo, s2hi;
            upk2(s[2*st], s1lo, s1hi); upk2(s[2*st+1], s2lo, s2hi);
            g_s0p[st][k]         = make_float2(s1lo, s2lo);
            g_s0p[st][k + CHAIN] = make_float2(s1hi, s2hi);
        }
        if (i + 1 < CHAIN) {
            ull f[10];
#pragma unroll
            for (int st = 0; st < 5; st++) {
                float2 flo = g_fp[st][k];
                float2 fhi = g_fp[st][k + CHAIN];
                f[2*st]   = pk2(flo.x, fhi.x);
                f[2*st+1] = pk2(flo.y, fhi.y);
            }
            ull ns[10];
#pragma unroll
            for (int r = 0; r < 10; r++) {
                ull acc = f[r];
#pragma unroll
                for (int c = 0; c < 10; c++) acc = fma2(sM[r*10 + c], s[c], acc);
                ns[r] = acc;
            }
#pragma unroll
            for (int j = 0; j < 10; j++) s[j] = ns[j];
        }
    }
}

// ---------------- Phase 3: exact re-run with reconstructed initial states ----------------
__global__ void __launch_bounds__(TPB, 4) eq_phase3_kernel(const float* __restrict__ x,
                                                           float* __restrict__ y) {
    extern __shared__ float sm[];
    float* sx = sm;                      // [CHUNK][RPAD] input tile
    float* sy = sm + CHUNK * RPAD;       // [CHUNK][RPAD] output tile
    const int t = threadIdx.x;
    const long base = (long)blockIdx.x * (BLKS_PER_CTA * LBLK);

    Coefs C; load_coefs(C);
    const int b0i = blockIdx.x * BLKS_PER_CTA + 2 * t;
    ull s1[5], s2[5];
#pragma unroll
    for (int i = 0; i < 5; i++) {
        float4 v = *(const float4*)&g_s0p[i][b0i];   // (s1_lo, s2_lo, s1_hi, s2_hi)
        s1[i] = pk2(v.x, v.z);
        s2[i] = pk2(v.y, v.w);
    }

    float4 pf[8];
#pragma unroll
    for (int j = 0; j < 8; j++) {
        int idx = j * TPB + t; int br = idx >> 2, cg = idx & 3;
        pf[j] = *(const float4*)(x + base + (long)br * LBLK + cg * 4);
    }

    for (int q = 0; q < NCHUNK; q++) {
#pragma unroll
        for (int j = 0; j < 8; j++) {
            int idx = j * TPB + t; int br = idx >> 2, cg = idx & 3;
            float4 v = pf[j];
            sx[(cg*4+0)*RPAD + br] = v.x;
            sx[(cg*4+1)*RPAD + br] = v.y;
            sx[(cg*4+2)*RPAD + br] = v.z;
            sx[(cg*4+3)*RPAD + br] = v.w;
        }
        __syncthreads();
        if (q + 1 < NCHUNK) {
#pragma unroll
            for (int j = 0; j < 8; j++) {
                int idx = j * TPB + t; int br = idx >> 2, cg = idx & 3;
                pf[j] = *(const float4*)(x + base + (long)br * LBLK + (q+1) * CHUNK + cg * 4);
            }
        }
#pragma unroll
        for (int c = 0; c < CHUNK; c++) {
            ull u = *(const ull*)(sx + c * RPAD + 2 * t);
            ull o = cascade_step(C, u, s1, s2);
            *(ull*)(sy + c * RPAD + 2 * t) = o;              // STS.64
        }
        __syncthreads();
#pragma unroll
        for (int j = 0; j < 8; j++) {
            int idx = j * TPB + t; int br = idx >> 2, cg = idx & 3;
            float4 v;
            v.x = sy[(cg*4+0)*RPAD + br];
            v.y = sy[(cg*4+1)*RPAD + br];
            v.z = sy[(cg*4+2)*RPAD + br];
            v.w = sy[(cg*4+3)*RPAD + br];
            *(float4*)(y + base + (long)br * LBLK + q * CHUNK + cg * 4) = v;
        }
        __syncthreads();
    }
}

// ---------------- Launch ----------------
extern "C" void kernel_launch(void* const* d_in, const int* in_sizes, int n_in,
                              void* d_out, int out_size) {
    (void)in_sizes; (void)n_in; (void)out_size;
    const float* x  = (const float*)d_in[0];
    const float* eq = (const float*)d_in[1];
    float* y = (float*)d_out;

    const int smem1 = CHUNK * RPAD * (int)sizeof(float);        // 16512 B
    const int smem3 = 2 * CHUNK * RPAD * (int)sizeof(float);    // 33024 B
    cudaFuncSetAttribute((const void*)eq_phase1_kernel,
                         cudaFuncAttributeMaxDynamicSharedMemorySize, smem1);
    cudaFuncSetAttribute((const void*)eq_phase3_kernel,
                         cudaFuncAttributeMaxDynamicSharedMemorySize, smem3);

    eq_setup_kernel<<<1, 128>>>(eq);
    eq_phase1_kernel<<<NCTA, TPB, smem1>>>(x);
    eq_scan_kernel<<<NBLK / (2 * CHAIN * 128), 128>>>();        // 64 CTAs
    eq_phase3_kernel<<<NCTA, TPB, smem3>>>(x, y);
}

// round 4
// speedup vs baseline: 1.0683x; 1.0683x over previous
#include <cuda_runtime.h>
#include <math.h>

// ---------------- Problem constants ----------------
#define BCH   8
#define NS    2097152
#define LBLK  128                 // samples per block
#define KPC   (NS/LBLK)           // 16384 blocks per channel
#define NBLK  (BCH*KPC)           // 131072 blocks total
#define TPB   128                 // threads per CTA (phase kernels)
#define BLKS_PER_CTA (2*TPB)      // 256 blocks per CTA (f32x2 pairing, adjacent)
#define NCTA  (NBLK/BLKS_PER_CTA) // 512 CTAs
#define CHUNK 16                  // samples staged per chunk
#define NCHUNK (LBLK/CHUNK)       // 8 chunks
#define RPAD  258                 // column stride (even for LDS.64, conflict-free)
#define DTR   14                  // warmup depth: 0.397^14 ~ 2.4e-6
#define CHAIN 4                   // blocks propagated serially per scan chain
#define SCAN_TPB 128
#define NSCAN_CTA (NBLK/(2*CHAIN*SCAN_TPB))   // 128 CTAs
#define PI_D  3.14159265358979323846
#define SR_D  44100.0
// float constants: log2(10)/40, 2*pi/44100
#define LOG2_10_OVER_40 0.08304820237218407f
#define W0_SCALE        1.42475857305659546e-4f

// ---------------- Device scratch ----------------
__device__ float2 g_fp[5][NBLK];       // zero-state final state per block, per stage (s1,s2)
__device__ float2 g_s0p[5][NBLK];      // reconstructed initial state per block, per stage

typedef unsigned long long ull;

// ---------------- f32x2 packed math (sm_103a) ----------------
__device__ __forceinline__ ull pk2(float lo, float hi) {
    ull r; asm("mov.b64 %0, {%1,%2};" : "=l"(r) : "f"(lo), "f"(hi)); return r;
}
__device__ __forceinline__ void upk2(ull v, float& lo, float& hi) {
    asm("mov.b64 {%0,%1}, %2;" : "=f"(lo), "=f"(hi) : "l"(v));
}
__device__ __forceinline__ ull fma2(ull a, ull b, ull c) {
    ull d; asm("fma.rn.f32x2 %0, %1, %2, %3;" : "=l"(d) : "l"(a), "l"(b), "l"(c)); return d;
}
__device__ __forceinline__ ull mul2(ull a, ull b) {
    ull d; asm("mul.rn.f32x2 %0, %1, %2;" : "=l"(d) : "l"(a), "l"(b)); return d;
}

// ---------------- Cascade coefficients (computed inline, float) ----------------
struct Coefs { ull b0[5], p1[5], p2[5], na1[5], na2[5]; };

__device__ __forceinline__ void compute_coefs(const float* __restrict__ eq, Coefs& C) {
#pragma unroll
    for (int i = 0; i < 5; i++) {
        float g  = eq[i*3+0], fc = eq[i*3+1], q = eq[i*3+2];
        float Av = exp2f(g * LOG2_10_OVER_40);
        float w0 = fc * W0_SCALE;
        float s  = sinf(w0), c = cosf(w0);
        float al = s / (2.0f * q);
        float b0, b1, b2, a0, a1, a2;
        if (i == 0 || i == 4) {
            float sgn = (i == 4) ? 1.0f : -1.0f;
            float sA = sqrtf(Av);
            b0 = Av * ((Av + 1.0f) + sgn * (Av - 1.0f) * c + 2.0f * sA * al);
            b1 = -2.0f * sgn * Av * ((Av - 1.0f) + sgn * (Av + 1.0f) * c);
            b2 = Av * ((Av + 1.0f) + sgn * (Av - 1.0f) * c - 2.0f * sA * al);
            a0 = (Av + 1.0f) - sgn * (Av - 1.0f) * c + 2.0f * sA * al;
            a1 = 2.0f * sgn * ((Av - 1.0f) - sgn * (Av + 1.0f) * c);
            a2 = (Av + 1.0f) - sgn * (Av - 1.0f) * c - 2.0f * sA * al;
        } else {
            b0 = 1.0f + al * Av; b1 = -2.0f * c; b2 = 1.0f - al * Av;
            a0 = 1.0f + al / Av; a1 = -2.0f * c; a2 = 1.0f - al / Av;
        }
        float inv = 1.0f / a0;
        float b0n = b0 * inv, b1n = b1 * inv, b2n = b2 * inv;
        float a1n = a1 * inv, a2n = a2 * inv;
        float p1 = b1n - a1n * b0n, p2 = b2n - a2n * b0n;
        C.b0[i]  = pk2(b0n, b0n);
        C.p1[i]  = pk2(p1, p1);
        C.p2[i]  = pk2(p2, p2);
        C.na1[i] = pk2(-a1n, -a1n);
        C.na2[i] = pk2(-a2n, -a2n);
    }
}

// one sample through the 5-biquad cascade (state-space form, 4-cyc state chain)
__device__ __forceinline__ ull cascade_step(const Coefs& C, ull u, ull s1[5], ull s2[5]) {
#pragma unroll
    for (int i = 0; i < 5; i++) {
        ull y   = fma2(C.b0[i], u, s1[i]);
        ull tt  = fma2(C.p1[i], u, s2[i]);
        ull w   = mul2(C.p2[i], u);
        ull s1n = fma2(C.na1[i], s1[i], tt);
        s2[i]   = fma2(C.na2[i], s1[i], w);
        s1[i]   = s1n;
        u = y;
    }
    return u;
}

// ---------------- Phase 1: zero-state recurrence, emit final states ----------------
__global__ void __launch_bounds__(TPB, 5) eq_phase1_kernel(const float* __restrict__ x,
                                                           const float* __restrict__ eq) {
    extern __shared__ float sx[];                 // [CHUNK][RPAD]
    const int t = threadIdx.x;
    const long base = (long)blockIdx.x * (BLKS_PER_CTA * LBLK);

    Coefs C; compute_coefs(eq, C);
    ull s1[5] = {0,0,0,0,0}, s2[5] = {0,0,0,0,0};

#pragma unroll 1
    for (int q = 0; q < NCHUNK; q++) {
#pragma unroll
        for (int j = 0; j < 8; j++) {
            int idx = j * TPB + t; int br = idx >> 2, cg = idx & 3;
            float4 v = *(const float4*)(x + base + (long)br * LBLK + q * CHUNK + cg * 4);
            sx[(cg*4+0)*RPAD + br] = v.x;
            sx[(cg*4+1)*RPAD + br] = v.y;
            sx[(cg*4+2)*RPAD + br] = v.z;
            sx[(cg*4+3)*RPAD + br] = v.w;
        }
        __syncthreads();
#pragma unroll
        for (int c = 0; c < CHUNK; c++) {
            ull u = *(const ull*)(sx + c * RPAD + 2 * t);   // LDS.64: both lanes
            (void)cascade_step(C, u, s1, s2);
        }
        __syncthreads();
    }

    const int b0i = blockIdx.x * BLKS_PER_CTA + 2 * t;      // adjacent pair
#pragma unroll
    for (int i = 0; i < 5; i++) {
        float s1lo, s1hi, s2lo, s2hi;
        upk2(s1[i], s1lo, s1hi); upk2(s2[i], s2lo, s2hi);
        *(float4*)&g_fp[i][b0i] = make_float4(s1lo, s2lo, s1hi, s2hi);
    }
}

// ---------------- Phase 2: M = A^128 (double, in-CTA) + chained scan ----------------
__global__ void __launch_bounds__(SCAN_TPB) eq_scan_kernel(const float* __restrict__ eq) {
    __shared__ double sc[5][5];
    __shared__ double Abuf[100], Ma[100], Mb[100];
    __shared__ ull sM[100];
    const int t = threadIdx.x;

    // ---- prologue: double-precision coefs, A, M = A^128 ----
    if (t < 5) {
        int i = t;
        double g = (double)eq[i*3+0], fc = (double)eq[i*3+1], q = (double)eq[i*3+2];
        double Av = pow(10.0, g / 40.0);
        double w0 = 2.0 * PI_D * fc / SR_D;
        double al = sin(w0) / (2.0 * q);
        double c  = cos(w0);
        double b0, b1, b2, a0, a1, a2;
        if (i == 0 || i == 4) {
            double sgn = (i == 4) ? 1.0 : -1.0;
            double sA = sqrt(Av);
            b0 = Av * ((Av + 1.0) + sgn * (Av - 1.0) * c + 2.0 * sA * al);
            b1 = -2.0 * sgn * Av * ((Av - 1.0) + sgn * (Av + 1.0) * c);
            b2 = Av * ((Av + 1.0) + sgn * (Av - 1.0) * c - 2.0 * sA * al);
            a0 = (Av + 1.0) - sgn * (Av - 1.0) * c + 2.0 * sA * al;
            a1 = 2.0 * sgn * ((Av - 1.0) - sgn * (Av + 1.0) * c);
            a2 = (Av + 1.0) - sgn * (Av - 1.0) * c - 2.0 * sA * al;
        } else {
            b0 = 1.0 + al * Av; b1 = -2.0 * c; b2 = 1.0 - al * Av;
            a0 = 1.0 + al / Av; a1 = -2.0 * c; a2 = 1.0 - al / Av;
        }
        sc[i][0] = b0/a0; sc[i][1] = b1/a0; sc[i][2] = b2/a0;
        sc[i][3] = a1/a0; sc[i][4] = a2/a0;
    }
    __syncthreads();
    if (t == 0) {
        double U[10]; for (int j = 0; j < 10; j++) U[j] = 0.0;
        for (int j = 0; j < 100; j++) Abuf[j] = 0.0;
        for (int i = 0; i < 5; i++) {
            double b0 = sc[i][0], b1 = sc[i][1], b2 = sc[i][2], a1 = sc[i][3], a2 = sc[i][4];
            double p1 = b1 - a1 * b0, p2 = b2 - a2 * b0;
            for (int j = 0; j < 10; j++) {
                Abuf[(2*i)*10 + j]   += p1 * U[j];
                Abuf[(2*i+1)*10 + j] += p2 * U[j];
            }
            Abuf[(2*i)*10 + 2*i]     += -a1;
            Abuf[(2*i)*10 + 2*i + 1] += 1.0;
            Abuf[(2*i+1)*10 + 2*i]   += -a2;
            for (int j = 0; j < 10; j++) U[j] *= b0;
            U[2*i] += 1.0;
        }
    }
    __syncthreads();
    if (t < 100) Ma[t] = Abuf[t];
    __syncthreads();
    {
        double* src = Ma; double* dst = Mb;
        for (int s = 0; s < 7; s++) {          // A^(2^7) = A^128
            if (t < 100) {
                int r = t / 10, c = t % 10;
                double acc = 0.0;
                for (int k = 0; k < 10; k++) acc += src[r*10 + k] * src[k*10 + c];
                dst[t] = acc;
            }
            __syncthreads();
            double* tmp = src; src = dst; dst = tmp;
        }
        if (t < 100) { float m = (float)src[t]; sM[t] = pk2(m, m); }
    }
    __syncthreads();

    // ---- chained scan: thread handles chains lo=[8p..8p+3], hi=[8p+4..8p+7] ----
    const int p = blockIdx.x * SCAN_TPB + t;
    const int j_lo = (2 * p) * CHAIN;
    const int ch0 = j_lo & ~(KPC - 1);         // channel start (chains never straddle)

    ull s[10];
#pragma unroll
    for (int j = 0; j < 10; j++) s[j] = 0;

    // Warmup: k = j_lo-DTR .. j_lo-1 :  s = M*s + f[k]  (hi lane uses k+CHAIN)
#pragma unroll 1
    for (int k = j_lo - DTR; k < j_lo; k++) {
        ull f[10];
#pragma unroll
        for (int i = 0; i < 5; i++) {
            float2 flo = (k >= ch0) ? g_fp[i][k] : make_float2(0.f, 0.f);
            float2 fhi = (k + CHAIN >= ch0) ? g_fp[i][k + CHAIN] : make_float2(0.f, 0.f);
            f[2*i]   = pk2(flo.x, fhi.x);
            f[2*i+1] = pk2(flo.y, fhi.y);
        }
        ull ns[10];
#pragma unroll
        for (int r = 0; r < 10; r++) {
            ull acc = f[r];
#pragma unroll
            for (int c = 0; c < 10; c++) acc = fma2(sM[r*10 + c], s[c], acc);
            ns[r] = acc;
        }
#pragma unroll
        for (int j = 0; j < 10; j++) s[j] = ns[j];
    }

    // Emit + propagate through CHAIN blocks
#pragma unroll 1
    for (int i = 0; i < CHAIN; i++) {
        int k = j_lo + i;
#pragma unroll
        for (int st = 0; st < 5; st++) {
            float s1lo, s1hi, s2lo, s2hi;
            upk2(s[2*st], s1lo, s1hi); upk2(s[2*st+1], s2lo, s2hi);
            g_s0p[st][k]         = make_float2(s1lo, s2lo);
            g_s0p[st][k + CHAIN] = make_float2(s1hi, s2hi);
        }
        if (i + 1 < CHAIN) {
            ull f[10];
#pragma unroll
            for (int st = 0; st < 5; st++) {
                float2 flo = g_fp[st][k];
                float2 fhi = g_fp[st][k + CHAIN];
                f[2*st]   = pk2(flo.x, fhi.x);
                f[2*st+1] = pk2(flo.y, fhi.y);
            }
            ull ns[10];
#pragma unroll
            for (int r = 0; r < 10; r++) {
                ull acc = f[r];
#pragma unroll
                for (int c = 0; c < 10; c++) acc = fma2(sM[r*10 + c], s[c], acc);
                ns[r] = acc;
            }
#pragma unroll
            for (int j = 0; j < 10; j++) s[j] = ns[j];
        }
    }
}

// ---------------- Phase 3: exact re-run with reconstructed initial states ----------------
__global__ void __launch_bounds__(TPB, 5) eq_phase3_kernel(const float* __restrict__ x,
                                                           const float* __restrict__ eq,
                                                           float* __restrict__ y) {
    extern __shared__ float sm[];
    float* sx = sm;                      // [CHUNK][RPAD] input tile
    float* sy = sm + CHUNK * RPAD;       // [CHUNK][RPAD] output tile
    const int t = threadIdx.x;
    const long base = (long)blockIdx.x * (BLKS_PER_CTA * LBLK);

    Coefs C; compute_coefs(eq, C);
    const int b0i = blockIdx.x * BLKS_PER_CTA + 2 * t;
    ull s1[5], s2[5];
#pragma unroll
    for (int i = 0; i < 5; i++) {
        float4 v = *(const float4*)&g_s0p[i][b0i];   // (s1_lo, s2_lo, s1_hi, s2_hi)
        s1[i] = pk2(v.x, v.z);
        s2[i] = pk2(v.y, v.w);
    }

#pragma unroll 1
    for (int q = 0; q < NCHUNK; q++) {
#pragma unroll
        for (int j = 0; j < 8; j++) {
            int idx = j * TPB + t; int br = idx >> 2, cg = idx & 3;
            float4 v = *(const float4*)(x + base + (long)br * LBLK + q * CHUNK + cg * 4);
            sx[(cg*4+0)*RPAD + br] = v.x;
            sx[(cg*4+1)*RPAD + br] = v.y;
            sx[(cg*4+2)*RPAD + br] = v.z;
            sx[(cg*4+3)*RPAD + br] = v.w;
        }
        __syncthreads();
#pragma unroll
        for (int c = 0; c < CHUNK; c++) {
            ull u = *(const ull*)(sx + c * RPAD + 2 * t);
            ull o = cascade_step(C, u, s1, s2);
            *(ull*)(sy + c * RPAD + 2 * t) = o;              // STS.64
        }
        __syncthreads();
#pragma unroll
        for (int j = 0; j < 8; j++) {
            int idx = j * TPB + t; int br = idx >> 2, cg = idx & 3;
            float4 v;
            v.x = sy[(cg*4+0)*RPAD + br];
            v.y = sy[(cg*4+1)*RPAD + br];
            v.z = sy[(cg*4+2)*RPAD + br];
            v.w = sy[(cg*4+3)*RPAD + br];
            *(float4*)(y + base + (long)br * LBLK + q * CHUNK + cg * 4) = v;
        }
        __syncthreads();
    }
}

// ---------------- Launch ----------------
extern "C" void kernel_launch(void* const* d_in, const int* in_sizes, int n_in,
                              void* d_out, int out_size) {
    (void)in_sizes; (void)n_in; (void)out_size;
    const float* x  = (const float*)d_in[0];
    const float* eq = (const float*)d_in[1];
    float* y = (float*)d_out;

    const int smem1 = CHUNK * RPAD * (int)sizeof(float);        // 16512 B
    const int smem3 = 2 * CHUNK * RPAD * (int)sizeof(float);    // 33024 B
    cudaFuncSetAttribute((const void*)eq_phase1_kernel,
                         cudaFuncAttributeMaxDynamicSharedMemorySize, smem1);
    cudaFuncSetAttribute((const void*)eq_phase3_kernel,
                         cudaFuncAttributeMaxDynamicSharedMemorySize, smem3);

    eq_phase1_kernel<<<NCTA, TPB, smem1>>>(x, eq);
    eq_scan_kernel<<<NSCAN_CTA, SCAN_TPB>>>(eq);
    eq_phase3_kernel<<<NCTA, TPB, smem3>>>(x, eq, y);
}